// round 17
// baseline (speedup 1.0000x reference)
#include <cuda_runtime.h>
#include <cuda_fp16.h>
#include <math.h>
#include <stdint.h>

#define TT 50
#define BB 256
#define DBEL 1024
#define DST 128
#define DACT 32
#define DHID 1024
#define DEMB 1024
#define GRU3 (3*DBEL)

static constexpr size_t OFF_BEL = 0;
static constexpr size_t OFF_PRS = (size_t)TT*BB*DBEL;
static constexpr size_t OFF_MP  = OFF_PRS + (size_t)TT*BB*DST;
static constexpr size_t OFF_SP  = OFF_MP  + (size_t)TT*BB*DST;
static constexpr size_t OFF_POS = OFF_SP  + (size_t)TT*BB*DST;
static constexpr size_t OFF_MQ  = OFF_POS + (size_t)TT*BB*DST;
static constexpr size_t OFF_SQ  = OFF_MQ  + (size_t)TT*BB*DST;

// ---- PADTILE format: 64-row x 32-col chunk stored as 64 x 40 halfs (5120 B, padded
// row image identical to the smem tile). chunk = (row/64)*(K/32) + (col/32);
// half-offset = chunk*2560 + (row%64)*40 + (col%32). Pads never read.
#define PT(N, K) ((size_t)((N)/64) * ((K)/32) * 2560)

__device__ __align__(128) __half tWsa_h[PT(DBEL,160)],    tWsa_l[PT(DBEL,160)];
__device__ __align__(128) __half tWih_h[PT(GRU3,DBEL)],   tWih_l[PT(GRU3,DBEL)];
__device__ __align__(128) __half tWhh_h[PT(GRU3,DBEL)],   tWhh_l[PT(GRU3,DBEL)];
__device__ __align__(128) __half tWpoh_h[PT(DHID,2048)],  tWpoh_l[PT(DHID,2048)];
__device__ __align__(128) __half tWpos_h[PT(2*DST,DHID)], tWpos_l[PT(2*DST,DHID)];
__device__ __align__(128) __half tWprh_h[PT(DHID,DBEL)],  tWprh_l[PT(DHID,DBEL)];
__device__ __align__(128) __half tWprs_h[PT(2*DST,DHID)], tWprs_l[PT(2*DST,DHID)];

__device__ __align__(128) __half Ax_p[PT(BB,DBEL)];
__device__ __align__(128) __half AbelI_p[PT(BB,DBEL)];
__device__ __align__(128) __half Abel_p[(size_t)TT*PT(BB,DBEL)];
__device__ __align__(128) __half Aobs_p[(size_t)TT*PT(BB,DEMB)];
__device__ __align__(128) __half Ahp_p[(size_t)TT*PT(BB,DHID)];

__device__ float g_gi[BB*GRU3];
__device__ float g_gh[BB*GRU3];
__device__ float g_hq1[BB*DHID];
__device__ float g_hq2[BB*DHID];
__device__ float g_belief[BB*DBEL];
__device__ int   g_ctr[2*TT];

__device__ __forceinline__ float eluf(float x)   { return x > 0.f ? x : expm1f(x); }
__device__ __forceinline__ float splusf(float x) { return fmaxf(x, 0.f) + log1pf(expf(-fabsf(x))); }
__device__ __forceinline__ float sigf(float x)   { return 1.f / (1.f + expf(-x)); }

// ---- PTX ----
__device__ __forceinline__ void bulkcp(uint32_t dst, const void* src, uint32_t bytes, uint32_t mbar) {
    asm volatile("cp.async.bulk.shared::cluster.global.mbarrier::complete_tx::bytes [%0], [%1], %2, [%3];"
        :: "r"(dst), "l"(src), "r"(bytes), "r"(mbar) : "memory");
}
#define MBAR_INIT(a, c) \
    asm volatile("mbarrier.init.shared.b64 [%0], %1;" :: "r"((uint32_t)(a)), "r"((uint32_t)(c)) : "memory")
#define MBAR_EXPECT(a, b) \
    asm volatile("mbarrier.arrive.expect_tx.shared.b64 _, [%0], %1;" :: "r"((uint32_t)(a)), "r"((uint32_t)(b)) : "memory")
#define MBAR_WAIT(a, p) do { \
    uint32_t _m = (uint32_t)(a); uint32_t _p = (uint32_t)(p); uint32_t _d; \
    asm volatile("{\n\t.reg .pred q;\n\tmbarrier.try_wait.parity.acquire.cta.shared::cta.b64 q, [%1], %2;\n\tselp.b32 %0, 1, 0, q;\n\t}" \
        : "=r"(_d) : "r"(_m), "r"(_p) : "memory"); \
    if (!_d) { \
        asm volatile("{\n\t.reg .pred Q;\n\tWL_%=:\n\tmbarrier.try_wait.parity.acquire.cta.shared::cta.b64 Q, [%0], %1, 0x989680;\n\t@Q bra.uni WD_%=;\n\tbra.uni WL_%=;\n\tWD_%=:\n\t}" \
            :: "r"(_m), "r"(_p) : "memory"); \
    } } while (0)

__device__ __forceinline__ void ldsm4(uint32_t (&r)[4], uint32_t addr) {
    asm volatile("ldmatrix.sync.aligned.m8n8.x4.shared.b16 {%0,%1,%2,%3}, [%4];"
        : "=r"(r[0]), "=r"(r[1]), "=r"(r[2]), "=r"(r[3]) : "r"(addr));
}
__device__ __forceinline__ void mmah(float (&d)[4], const uint32_t (&a)[4], const uint32_t (&b)[2]) {
    asm volatile("mma.sync.aligned.m16n8k16.row.col.f32.f16.f16.f32 "
        "{%0,%1,%2,%3}, {%4,%5,%6,%7}, {%8,%9}, {%0,%1,%2,%3};"
        : "+f"(d[0]), "+f"(d[1]), "+f"(d[2]), "+f"(d[3])
        : "r"(a[0]), "r"(a[1]), "r"(a[2]), "r"(a[3]), "r"(b[0]), "r"(b[1]));
}

__device__ __forceinline__ void pack8h(const float* r, uint4& o)
{
    __half2 p0 = __floats2half2_rn(r[0], r[1]);
    __half2 p1 = __floats2half2_rn(r[2], r[3]);
    __half2 p2 = __floats2half2_rn(r[4], r[5]);
    __half2 p3 = __floats2half2_rn(r[6], r[7]);
    o = make_uint4(*reinterpret_cast<uint32_t*>(&p0), *reinterpret_cast<uint32_t*>(&p1),
                   *reinterpret_cast<uint32_t*>(&p2), *reinterpret_cast<uint32_t*>(&p3));
}

__device__ __forceinline__ size_t pt_idx(int ktpr, int row, int col)
{
    return ((size_t)(row >> 6) * ktpr + (col >> 5)) * 2560 + (row & 63) * 40 + (col & 31);
}
__device__ __forceinline__ void store_a4(__half* p, size_t idx, float4 v)
{
    *reinterpret_cast<__half2*>(p + idx)     = __floats2half2_rn(v.x, v.y);
    *reinterpret_cast<__half2*>(p + idx + 2) = __floats2half2_rn(v.z, v.w);
}

// in-kernel counter barrier; ALL blocks of the grid must be resident (single wave)
__device__ __forceinline__ void ctr_barrier(int* ctr, int n)
{
    __threadfence();
    __syncthreads();
    if (threadIdx.x == 0) {
        atomicAdd(ctr, 1);
        while (*((volatile int*)ctr) < n) __nanosleep(32);
    }
    __syncthreads();
    __threadfence();
}

// ---- GEMM core: 64x64 block, 4 warps of 32x32, BK=64 stages (2 chunks/stage) ----
enum { AT_TILED = 0, AT_TILED2 = 1, AT_STATE = 2, AT_ELUSUM = 3 };
enum { EPI_F32 = 0, EPI_TILEA = 1, EPI_HEADAT = 2, EPI_HEADST = 3 };

template<int ALOAD>
__device__ __forceinline__ void load_a8(
    int gm, int k, float* r,
    const float* A2f, int lda2, int K1,
    const float* st_mq, const float* st_sq, const float* st_eps,
    const float* st_nt, const float* st_prev)
{
    if (ALOAD == AT_ELUSUM) {
        const int base = gm * DHID + k;
#pragma unroll
        for (int i = 0; i < 8; i++)
            r[i] = eluf(g_hq1[base + i] + g_hq2[base + i]);
        return;
    }
    if (ALOAD == AT_STATE) {
        if (k < K1) {
            const float nt = st_nt[gm];
            const int base = gm * DST + k;
            if (st_mq) {
#pragma unroll
                for (int i = 0; i < 8; i++) {
                    float s = splusf(st_sq[base + i]) + 0.1f;
                    r[i] = (st_mq[base + i] + s * st_eps[base + i]) * nt;
                }
            } else {
#pragma unroll
                for (int i = 0; i < 8; i++) r[i] = st_prev[base + i] * nt;
            }
        } else {
            const float* p = A2f + (size_t)gm * lda2 + (k - K1);
            float4 v0 = *reinterpret_cast<const float4*>(p);
            float4 v1 = *reinterpret_cast<const float4*>(p + 4);
            r[0] = v0.x; r[1] = v0.y; r[2] = v0.z; r[3] = v0.w;
            r[4] = v1.x; r[5] = v1.y; r[6] = v1.z; r[7] = v1.w;
        }
    }
}

template<int EPI>
__device__ __forceinline__ void epi2(
    int kc, int r, int c, float v0, float v1,
    const float* bias, float* out, int ldout,
    float* mean_out, float* std_out, __half* oap)
{
    if (EPI == EPI_F32) {
        if (bias) { v0 += __ldg(bias + c); v1 += __ldg(bias + c + 1); }
        *reinterpret_cast<float2*>(out + (size_t)r * ldout + c) = make_float2(v0, v1);
    } else if (EPI == EPI_TILEA) {
        v0 = eluf(v0 + __ldg(bias + c));
        v1 = eluf(v1 + __ldg(bias + c + 1));
        *reinterpret_cast<__half2*>(oap + pt_idx(32, r, c)) = __floats2half2_rn(v0, v1);
    } else if (EPI == EPI_HEADAT) {
        float b0 = (kc == 0) ? __ldg(bias + c)     : 0.f;
        float b1 = (kc == 0) ? __ldg(bias + c + 1) : 0.f;
        if (c < DST) {
            atomicAdd(mean_out + (size_t)r * DST + c,     v0 + b0);
            atomicAdd(mean_out + (size_t)r * DST + c + 1, v1 + b1);
        } else {
            atomicAdd(std_out + (size_t)r * DST + (c - DST),     v0 + b0);
            atomicAdd(std_out + (size_t)r * DST + (c - DST) + 1, v1 + b1);
        }
    } else { // EPI_HEADST
        float w0 = v0 + __ldg(bias + c), w1 = v1 + __ldg(bias + c + 1);
        if (c < DST) {
            mean_out[(size_t)r * DST + c]     = w0;
            mean_out[(size_t)r * DST + c + 1] = w1;
        } else {
            std_out[(size_t)r * DST + (c - DST)]     = splusf(w0) + 0.1f;
            std_out[(size_t)r * DST + (c - DST) + 1] = splusf(w1) + 0.1f;
        }
    }
}

// smem: 2 stage buffers x (A0 A1 Bh0 Bh1 Bl0 Bl1) x 5120 = 61440 B + 2 mbarriers
#define GEMM_SMEM 61472
template<int KC, int ALOAD, int EPI>
__device__ __forceinline__ void gemm64(
    int mb, int nb, int kc,
    const __half* ap1, const __half* ap2, int ks1,
    const float* A2f, int lda2, int K1,
    const float* st_mq, const float* st_sq, const float* st_eps,
    const float* st_nt, const float* st_prev,
    const __half* bh, const __half* bl, int kspmb,
    const float* bias, float* out, int ldout,
    float* mean_out, float* std_out, __half* oap)
{
    constexpr int NCH  = KC / 32;
    constexpr int NSTG = (NCH + 1) / 2;
    constexpr bool TILEDA = (ALOAD == AT_TILED || ALOAD == AT_TILED2);
    extern __shared__ __align__(16) char dsm[];

    const int tid  = threadIdx.x;
    const int lane = tid & 31;
    const int wid  = tid >> 5;
    const int wm = (wid >> 1) * 32;
    const int wn = (wid & 1) * 32;
    const int ksbeg = kc * NCH;

    const uint32_t sb = (uint32_t)__cvta_generic_to_shared(dsm);
    const uint32_t CH  = 5120u;
    const uint32_t STG = 30720u;
    const uint32_t mb0 = sb + 61440u;

    if (tid == 0) { MBAR_INIT(mb0, 1); MBAR_INIT(mb0 + 8, 1); }
    __syncthreads();

    auto issue = [&](int s) {
        const int st = s & 1;
        const int n2 = (2 * s + 1 < NCH) ? 2 : 1;
        const uint32_t buf = sb + st * STG, mbar = mb0 + st * 8;
        MBAR_EXPECT(mbar, (uint32_t)n2 * (TILEDA ? 15360u : 10240u));
        for (int j = 0; j < n2; j++) {
            const int ks = ksbeg + 2 * s + j;
            if (TILEDA) {
                const __half* pa;
                if (ALOAD == AT_TILED2 && ks >= ks1) pa = ap2 + (size_t)(mb * 32 + (ks - ks1)) * 2560;
                else                                  pa = ap1 + (size_t)(mb * 32 + ks) * 2560;
                bulkcp(buf + j * CH, pa, 5120u, mbar);
            }
            bulkcp(buf + 2 * CH + j * CH, bh + (size_t)(nb * kspmb + ks) * 2560, 5120u, mbar);
            bulkcp(buf + 4 * CH + j * CH, bl + (size_t)(nb * kspmb + ks) * 2560, 5120u, mbar);
        }
    };
    auto fillA = [&](int s) {
        if (TILEDA) return;
        const int st = s & 1;
        const int n2 = (2 * s + 1 < NCH) ? 2 : 1;
        const int lrow = tid >> 1, lkb = (tid & 1) << 4;
        const int gm = mb * 64 + lrow;
        for (int j = 0; j < n2; j++) {
            __half* as = reinterpret_cast<__half*>(dsm + st * STG + j * CH);
#pragma unroll
            for (int q = 0; q < 2; q++) {
                float r8[8];
                load_a8<ALOAD>(gm, (ksbeg + 2 * s + j) * 32 + lkb + q * 8, r8,
                               A2f, lda2, K1, st_mq, st_sq, st_eps, st_nt, st_prev);
                uint4 pk; pack8h(r8, pk);
                *reinterpret_cast<uint4*>(&as[lrow * 40 + lkb + q * 8]) = pk;
            }
        }
    };

    if (tid == 0) { issue(0); if (NSTG > 1) issue(1); }
    fillA(0);
    if (NSTG > 1) fillA(1);
    __syncthreads();

    float acc[2][4][4];
#pragma unroll
    for (int i = 0; i < 2; i++)
#pragma unroll
        for (int j = 0; j < 4; j++)
#pragma unroll
            for (int q = 0; q < 4; q++) acc[i][j][q] = 0.f;

    const int amat = lane >> 3, arin = lane & 7;
    const int arowb = wm + ((amat & 1) << 3) + arin;
    const int acol  = (amat >> 1) << 3;
    const int brow = wn + ((lane >> 4) << 3) + (lane & 7);
    const int bcol = ((lane >> 3) & 1) << 3;

    int ph[2] = {0, 0};
#pragma unroll 1
    for (int s = 0; s < NSTG; s++) {
        const int cur = s & 1;
        MBAR_WAIT(mb0 + cur * 8, ph[cur]); ph[cur] ^= 1;
        const int n2 = (2 * s + 1 < NCH) ? 2 : 1;
#pragma unroll
        for (int j = 0; j < 2; j++) {
            if (j >= n2) break;
            const uint32_t aOff  = sb + cur * STG + j * CH;
            const uint32_t bhOff = sb + cur * STG + 2 * CH + j * CH;
            const uint32_t blOff = sb + cur * STG + 4 * CH + j * CH;
#pragma unroll
            for (int kk = 0; kk < 32; kk += 16) {
                uint32_t Am[2][4], Bh[4][2], Bl[4][2];
#pragma unroll
                for (int mf = 0; mf < 2; mf++) {
                    uint32_t off = (uint32_t)(((arowb + mf*16) * 40 + kk + acol) * 2);
                    ldsm4(Am[mf], aOff + off);
                }
#pragma unroll
                for (int nfp = 0; nfp < 2; nfp++) {
                    uint32_t off = (uint32_t)(((brow + nfp*16) * 40 + kk + bcol) * 2);
                    uint32_t rh[4], rl[4];
                    ldsm4(rh, bhOff + off);
                    ldsm4(rl, blOff + off);
                    Bh[nfp*2][0]   = rh[0]; Bh[nfp*2][1]   = rh[1];
                    Bh[nfp*2+1][0] = rh[2]; Bh[nfp*2+1][1] = rh[3];
                    Bl[nfp*2][0]   = rl[0]; Bl[nfp*2][1]   = rl[1];
                    Bl[nfp*2+1][0] = rl[2]; Bl[nfp*2+1][1] = rl[3];
                }
#pragma unroll
                for (int mf = 0; mf < 2; mf++)
#pragma unroll
                    for (int nf = 0; nf < 4; nf++) {
                        mmah(acc[mf][nf], Am[mf], Bh[nf]);
                        mmah(acc[mf][nf], Am[mf], Bl[nf]);
                    }
            }
        }
        __syncthreads();
        if (s + 2 < NSTG) {
            fillA(s + 2);
            if (tid == 0) issue(s + 2);
        }
    }

    const int gr = lane >> 2, gc = (lane & 3) << 1;
#pragma unroll
    for (int mf = 0; mf < 2; mf++)
#pragma unroll
        for (int nf = 0; nf < 4; nf++) {
            int r = mb * 64 + wm + mf * 16 + gr;
            int c = nb * 64 + wn + nf * 8 + gc;
            epi2<EPI>(kc, r,     c, acc[mf][nf][0], acc[mf][nf][1], bias, out, ldout, mean_out, std_out, oap);
            epi2<EPI>(kc, r + 8, c, acc[mf][nf][2], acc[mf][nf][3], bias, out, ldout, mean_out, std_out, oap);
        }
}

// ---- fused phase kernels (3 launches per step) ----
// L1: x tiles (64) + gh tiles (192) — independent work
__global__ void __launch_bounds__(128) k_xgh(
    const float* act, const float* nt, const float* mq, const float* sq,
    const float* eps, const float* prev, const float* b_sa,
    const __half* belp, const float* b_hh)
{
    if (blockIdx.x < 64) {
        int mb = blockIdx.x >> 4, nb = blockIdx.x & 15;
        gemm64<160, AT_STATE, EPI_TILEA>(mb, nb, 0,
            nullptr, nullptr, 0, act, DACT, DST, mq, sq, eps, nt, prev,
            tWsa_h, tWsa_l, 5,
            b_sa, nullptr, 0, nullptr, nullptr, Ax_p);
    } else {
        int r = blockIdx.x - 64;
        int mb = r / 48, nb = r % 48;
        gemm64<1024, AT_TILED, EPI_F32>(mb, nb, 0,
            belp, nullptr, 0, nullptr, 0, 0, nullptr, nullptr, nullptr, nullptr, nullptr,
            tWhh_h, tWhh_l, 32,
            b_hh, g_gh, GRU3, nullptr, nullptr, nullptr);
    }
}

// L2: gi tiles (192), counter barrier, then GRU combine on the same blocks
__global__ void __launch_bounds__(128) k_gigru(
    const float* b_ih, float* belout, __half* abp, int* ctr)
{
    int mb = blockIdx.x / 48, nb = blockIdx.x % 48;
    gemm64<1024, AT_TILED, EPI_F32>(mb, nb, 0,
        Ax_p, nullptr, 0, nullptr, 0, 0, nullptr, nullptr, nullptr, nullptr, nullptr,
        tWih_h, tWih_l, 32,
        b_ih, g_gi, GRU3, nullptr, nullptr, nullptr);

    ctr_barrier(ctr, 192);

    const int nthr = 192 * 128;
    for (int i4 = (blockIdx.x * 128 + threadIdx.x) * 4; i4 < BB * DBEL; i4 += nthr * 4) {
        int m = i4 >> 10, j = i4 & 1023;
        const size_t base = (size_t)m * GRU3 + j;
        float4 gir = *reinterpret_cast<const float4*>(g_gi + base);
        float4 giz = *reinterpret_cast<const float4*>(g_gi + base + 1024);
        float4 gin = *reinterpret_cast<const float4*>(g_gi + base + 2048);
        float4 ghr = *reinterpret_cast<const float4*>(g_gh + base);
        float4 ghz = *reinterpret_cast<const float4*>(g_gh + base + 1024);
        float4 ghn = *reinterpret_cast<const float4*>(g_gh + base + 2048);
        float4 b   = *reinterpret_cast<const float4*>(g_belief + i4);
        float4 h;
        { float r = sigf(gir.x + ghr.x), z = sigf(giz.x + ghz.x);
          h.x = (1.f - z) * tanhf(gin.x + r * ghn.x) + z * b.x; }
        { float r = sigf(gir.y + ghr.y), z = sigf(giz.y + ghz.y);
          h.y = (1.f - z) * tanhf(gin.y + r * ghn.y) + z * b.y; }
        { float r = sigf(gir.z + ghr.z), z = sigf(giz.z + ghz.z);
          h.z = (1.f - z) * tanhf(gin.z + r * ghn.z) + z * b.z; }
        { float r = sigf(gir.w + ghr.w), z = sigf(giz.w + ghz.w);
          h.w = (1.f - z) * tanhf(gin.w + r * ghn.w) + z * b.w; }
        *reinterpret_cast<float4*>(g_belief + i4) = h;
        *reinterpret_cast<float4*>(belout + i4)  = h;
        store_a4(abp, pt_idx(32, m, j), h);
    }
}

// L3: hq tiles (128, split-K=2), counter barrier, then one head tile per block
__global__ void __launch_bounds__(128) k_hqhead(
    const __half* belp, const __half* obsp, const float* b_poh,
    const float* b_pos, float* mqo, float* sqo, int* ctr)
{
    {
        int kc = blockIdx.x >> 6;
        int r = blockIdx.x & 63;
        int mb = r >> 4, nb = r & 15;
        gemm64<1024, AT_TILED2, EPI_F32>(mb, nb, kc,
            belp, obsp, 32, nullptr, 0, 0, nullptr, nullptr, nullptr, nullptr, nullptr,
            tWpoh_h, tWpoh_l, 64,
            kc == 0 ? b_poh : nullptr,
            kc == 0 ? g_hq1 : g_hq2, DHID,
            nullptr, nullptr, nullptr);
    }

    ctr_barrier(ctr, 128);

    {
        int kc = blockIdx.x >> 4;
        int r = blockIdx.x & 15;
        int mb = r >> 2, nb = r & 3;
        gemm64<128, AT_ELUSUM, EPI_HEADAT>(mb, nb, kc,
            nullptr, nullptr, 0, nullptr, 0, 0, nullptr, nullptr, nullptr, nullptr, nullptr,
            tWpos_h, tWpos_l, 32,
            b_pos, nullptr, 0, mqo, sqo, nullptr);
    }
}

__global__ void __launch_bounds__(128) k_prh(const float* b_prh)
{
    int mb = blockIdx.x >> 4, nb = blockIdx.x & 15;
    gemm64<1024, AT_TILED, EPI_TILEA>(mb, nb, 0,
        Abel_p, nullptr, 0, nullptr, 0, 0, nullptr, nullptr, nullptr, nullptr, nullptr,
        tWprh_h, tWprh_l, 32,
        b_prh, nullptr, 0, nullptr, nullptr, Ahp_p);
}

__global__ void __launch_bounds__(128) k_prs(const float* b_prs, float* mp, float* sp)
{
    int mb = blockIdx.x >> 2, nb = blockIdx.x & 3;
    gemm64<1024, AT_TILED, EPI_HEADST>(mb, nb, 0,
        Ahp_p, nullptr, 0, nullptr, 0, 0, nullptr, nullptr, nullptr, nullptr, nullptr,
        tWprs_h, tWprs_l, 32,
        b_prs, nullptr, 0, mp, sp, nullptr);
}

// ---- elementwise ----
__global__ void conv_w(const float* __restrict__ W, __half* th, __half* tl, int N, int K)
{
    int e2 = (blockIdx.x * 256 + threadIdx.x) * 2;
    if (e2 >= N * K) return;
    int n = e2 / K, k = e2 % K;
    float v0 = __ldg(W + e2), v1 = __ldg(W + e2 + 1);
    __half h0 = __float2half_rn(v0), h1 = __float2half_rn(v1);
    __half l0 = __float2half_rn(v0 - __half2float(h0));
    __half l1 = __float2half_rn(v1 - __half2float(h1));
    size_t idx = ((size_t)(n >> 6) * (K >> 5) + (k >> 5)) * 2560 + (n & 63) * 40 + (k & 31);
    *reinterpret_cast<__half2*>(th + idx) = __halves2half2(h0, h1);
    *reinterpret_cast<__half2*>(tl + idx) = __halves2half2(l0, l1);
}

__global__ void conv_a(const float* __restrict__ X, __half* tp, int N, int K)
{
    int e4 = (blockIdx.x * 256 + threadIdx.x) * 4;
    if (e4 >= N * K) return;
    int n = e4 / K, k = e4 % K;
    float4 v = __ldg(reinterpret_cast<const float4*>(X + e4));
    size_t idx = ((size_t)(n >> 6) * (K >> 5) + (k >> 5)) * 2560 + (n & 63) * 40 + (k & 31);
    store_a4(tp, idx, v);
}

__global__ void k_init(const float* __restrict__ prevb, float* __restrict__ out)
{
    int i4 = (blockIdx.x * 128 + threadIdx.x) * 4;
    if (i4 == 0)
        for (int q = 0; q < 2 * TT; q++) g_ctr[q] = 0;
    if (i4 < 2 * TT * BB * DST)
        *reinterpret_cast<float4*>(out + OFF_MQ + i4) = make_float4(0.f, 0.f, 0.f, 0.f);
    if (i4 < BB * DBEL) {
        float4 v = __ldg(reinterpret_cast<const float4*>(prevb + i4));
        *reinterpret_cast<float4*>(g_belief + i4) = v;
        int m = i4 >> 10, k = i4 & 1023;
        store_a4(AbelI_p, pt_idx(32, m, k), v);
    }
}

__global__ void k_sample(float* __restrict__ out,
                         const float* __restrict__ ep, const float* __restrict__ eq)
{
    int i = (blockIdx.x * 128 + threadIdx.x) * 4;
    if (i >= TT * BB * DST) return;
    float4 mp = *reinterpret_cast<const float4*>(out + OFF_MP + i);
    float4 sp = *reinterpret_cast<const float4*>(out + OFF_SP + i);
    float4 e1 = __ldg(reinterpret_cast<const float4*>(ep + i));
    float4 mq = *reinterpret_cast<const float4*>(out + OFF_MQ + i);
    float4 sq = *reinterpret_cast<const float4*>(out + OFF_SQ + i);
    float4 e2 = __ldg(reinterpret_cast<const float4*>(eq + i));
    float4 prs, pos, sqo;
    prs.x = mp.x + sp.x * e1.x; prs.y = mp.y + sp.y * e1.y;
    prs.z = mp.z + sp.z * e1.z; prs.w = mp.w + sp.w * e1.w;
    sqo.x = splusf(sq.x) + 0.1f; sqo.y = splusf(sq.y) + 0.1f;
    sqo.z = splusf(sq.z) + 0.1f; sqo.w = splusf(sq.w) + 0.1f;
    pos.x = mq.x + sqo.x * e2.x; pos.y = mq.y + sqo.y * e2.y;
    pos.z = mq.z + sqo.z * e2.z; pos.w = mq.w + sqo.w * e2.w;
    *reinterpret_cast<float4*>(out + OFF_PRS + i) = prs;
    *reinterpret_cast<float4*>(out + OFF_SQ  + i) = sqo;
    *reinterpret_cast<float4*>(out + OFF_POS + i) = pos;
}

// ---- host ----
extern "C" void kernel_launch(void* const* d_in, const int* in_sizes, int n_in,
                              void* d_out, int out_size)
{
    (void)in_sizes; (void)n_in; (void)out_size;
    const float* prev_state   = (const float*)d_in[0];
    const float* actions      = (const float*)d_in[1];
    const float* prev_belief  = (const float*)d_in[2];
    const float* observations = (const float*)d_in[3];
    const float* nonterminals = (const float*)d_in[4];
    const float* prior_noise  = (const float*)d_in[5];
    const float* post_noise   = (const float*)d_in[6];
    const float* W_sa  = (const float*)d_in[7];
    const float* b_sa  = (const float*)d_in[8];
    const float* w_ih  = (const float*)d_in[9];
    const float* b_ih  = (const float*)d_in[10];
    const float* w_hh  = (const float*)d_in[11];
    const float* b_hh  = (const float*)d_in[12];
    const float* W_prh = (const float*)d_in[13];
    const float* b_prh = (const float*)d_in[14];
    const float* W_prs = (const float*)d_in[15];
    const float* b_prs = (const float*)d_in[16];
    const float* W_poh = (const float*)d_in[17];
    const float* b_poh = (const float*)d_in[18];
    const float* W_pos = (const float*)d_in[19];
    const float* b_pos = (const float*)d_in[20];
    float* out = (float*)d_out;

    cudaFuncSetAttribute(k_xgh,    cudaFuncAttributeMaxDynamicSharedMemorySize, GEMM_SMEM);
    cudaFuncSetAttribute(k_gigru,  cudaFuncAttributeMaxDynamicSharedMemorySize, GEMM_SMEM);
    cudaFuncSetAttribute(k_hqhead, cudaFuncAttributeMaxDynamicSharedMemorySize, GEMM_SMEM);
    cudaFuncSetAttribute(k_prh,    cudaFuncAttributeMaxDynamicSharedMemorySize, GEMM_SMEM);
    cudaFuncSetAttribute(k_prs,    cudaFuncAttributeMaxDynamicSharedMemorySize, GEMM_SMEM);

    __half *p_wsa_h, *p_wsa_l, *p_wih_h, *p_wih_l, *p_whh_h, *p_whh_l,
           *p_wpoh_h, *p_wpoh_l, *p_wpos_h, *p_wpos_l, *p_wprh_h, *p_wprh_l,
           *p_wprs_h, *p_wprs_l, *p_abel, *p_abeli, *p_aobs;
    int* p_ctr;
    cudaGetSymbolAddress((void**)&p_wsa_h,  tWsa_h);  cudaGetSymbolAddress((void**)&p_wsa_l,  tWsa_l);
    cudaGetSymbolAddress((void**)&p_wih_h,  tWih_h);  cudaGetSymbolAddress((void**)&p_wih_l,  tWih_l);
    cudaGetSymbolAddress((void**)&p_whh_h,  tWhh_h);  cudaGetSymbolAddress((void**)&p_whh_l,  tWhh_l);
    cudaGetSymbolAddress((void**)&p_wpoh_h, tWpoh_h); cudaGetSymbolAddress((void**)&p_wpoh_l, tWpoh_l);
    cudaGetSymbolAddress((void**)&p_wpos_h, tWpos_h); cudaGetSymbolAddress((void**)&p_wpos_l, tWpos_l);
    cudaGetSymbolAddress((void**)&p_wprh_h, tWprh_h); cudaGetSymbolAddress((void**)&p_wprh_l, tWprh_l);
    cudaGetSymbolAddress((void**)&p_wprs_h, tWprs_h); cudaGetSymbolAddress((void**)&p_wprs_l, tWprs_l);
    cudaGetSymbolAddress((void**)&p_abel,  Abel_p);
    cudaGetSymbolAddress((void**)&p_abeli, AbelI_p);
    cudaGetSymbolAddress((void**)&p_aobs,  Aobs_p);
    cudaGetSymbolAddress((void**)&p_ctr,   g_ctr);

    auto cw = [](const float* W, __half* h, __half* l, int N, int K) {
        conv_w<<<(N * K / 2 + 255) / 256, 256>>>(W, h, l, N, K);
    };
    cw(W_sa,  p_wsa_h,  p_wsa_l,  DBEL, 160);
    cw(w_ih,  p_wih_h,  p_wih_l,  GRU3, DBEL);
    cw(w_hh,  p_whh_h,  p_whh_l,  GRU3, DBEL);
    cw(W_poh, p_wpoh_h, p_wpoh_l, DHID, 2048);
    cw(W_pos, p_wpos_h, p_wpos_l, 2*DST, DHID);
    cw(W_prh, p_wprh_h, p_wprh_l, DHID, DBEL);
    cw(W_prs, p_wprs_h, p_wprs_l, 2*DST, DHID);
    conv_a<<<(TT * BB * DEMB / 4 + 255) / 256, 256>>>(observations, p_aobs, TT * BB, DEMB);

    k_init<<<(2 * TT * BB * DST / 4 + 127) / 128, 128>>>(prev_belief, out);

    const size_t TSTEP = PT(BB, DBEL);
    for (int t = 0; t < TT; t++) {
        const float* act = actions      + (size_t)t * BB * DACT;
        const float* nt  = nonterminals + (size_t)t * BB;
        const float* mq  = (t == 0) ? nullptr : out + OFF_MQ + (size_t)(t-1) * BB * DST;
        const float* sq  = (t == 0) ? nullptr : out + OFF_SQ + (size_t)(t-1) * BB * DST;
        const float* ep  = (t == 0) ? nullptr : post_noise + (size_t)(t-1) * BB * DST;
        const __half* bpp = (t == 0) ? p_abeli : p_abel + (size_t)(t-1) * TSTEP;

        k_xgh   <<<256, 128, GEMM_SMEM>>>(act, nt, mq, sq, ep, prev_state, b_sa, bpp, b_hh);
        k_gigru <<<192, 128, GEMM_SMEM>>>(b_ih,
                                          out + OFF_BEL + (size_t)t * BB * DBEL,
                                          p_abel + (size_t)t * TSTEP,
                                          p_ctr + 2 * t);
        k_hqhead<<<128, 128, GEMM_SMEM>>>(p_abel + (size_t)t * TSTEP,
                                          p_aobs + (size_t)t * TSTEP,
                                          b_poh, b_pos,
                                          out + OFF_MQ + (size_t)t * BB * DST,
                                          out + OFF_SQ + (size_t)t * BB * DST,
                                          p_ctr + 2 * t + 1);
    }

    k_prh<<<3200, 128, GEMM_SMEM>>>(b_prh);
    k_prs<<<800, 128, GEMM_SMEM>>>(b_prs, out + OFF_MP, out + OFF_SP);
    k_sample<<<(TT * BB * DST / 4 + 127) / 128, 128>>>(out, prior_noise, post_noise);
}